// round 14
// baseline (speedup 1.0000x reference)
#include <cuda_runtime.h>
#include <cuda_bf16.h>

#define D 128
#define N_MAX 50016
#define BM 128
#define LR (D + 4)   // padded shared row stride (floats)

__device__ float g_deg[N_MAX];
__device__ float g_norm[N_MAX];
__device__ float g_agg[(size_t)N_MAX * D];
__device__ float g_M[D * D];

static constexpr float ALPHA = 0.1f;

// ---------------------------------------------------------------------------
// Zero scratch (agg + deg). Graph is replayed, so this runs every launch.
// ---------------------------------------------------------------------------
__global__ void zero_kernel(int n) {
    int i = blockIdx.x * blockDim.x + threadIdx.x;
    int stride = gridDim.x * blockDim.x;
    int tot4 = n * D / 4;
    float4 z = make_float4(0.f, 0.f, 0.f, 0.f);
    for (int j = i; j < tot4; j += stride)
        reinterpret_cast<float4*>(g_agg)[j] = z;
    for (int j = i; j < n; j += stride)
        g_deg[j] = 0.f;
}

// ---------------------------------------------------------------------------
// In-degree. 4 edges per thread via int4 load.
// ---------------------------------------------------------------------------
__global__ void degree_kernel(const int* __restrict__ dst, int E) {
    int t = blockIdx.x * blockDim.x + threadIdx.x;
    int e4 = E >> 2;
    if (t < e4) {
        int4 d = reinterpret_cast<const int4*>(dst)[t];
        atomicAdd(&g_deg[d.x], 1.0f);
        atomicAdd(&g_deg[d.y], 1.0f);
        atomicAdd(&g_deg[d.z], 1.0f);
        atomicAdd(&g_deg[d.w], 1.0f);
    }
    int tail = E & 3;
    if (t < tail) atomicAdd(&g_deg[dst[e4 * 4 + t]], 1.0f);
}

// ---------------------------------------------------------------------------
// norm = clip(deg,1)^-0.5, fused with M = (1-beta)*I + beta*W1
// ---------------------------------------------------------------------------
__global__ void norm_and_m_kernel(const float* __restrict__ w, float beta,
                                  int n) {
    int i = blockIdx.x * blockDim.x + threadIdx.x;
    if (i < n) g_norm[i] = rsqrtf(fmaxf(g_deg[i], 1.0f));
    if (i < D * D) {
        float v = beta * w[i];
        if ((i / D) == (i % D)) v += (1.0f - beta);
        g_M[i] = v;
    }
}

// ---------------------------------------------------------------------------
// Edge scatter: agg[dst] += feat[src] * norm[src]
// One warp per edge: 1 warp-wide LDG.128 (512B row) + 1 warp-wide RED.128.
// Indices + norm loaded once (lanes 0/1), shfl-broadcast.
// Vectorized RED (sm_90+) quarters RED instruction count vs scalar atomics.
// ---------------------------------------------------------------------------
__global__ void scatter_kernel(const float* __restrict__ feat,
                               const int* __restrict__ src,
                               const int* __restrict__ dst, int E) {
    int warp = (blockIdx.x * blockDim.x + threadIdx.x) >> 5;
    int lane = threadIdx.x & 31;
    if (warp >= E) return;

    int idx = 0;
    if (lane == 0) idx = __ldg(&src[warp]);
    else if (lane == 1) idx = __ldg(&dst[warp]);
    int s = __shfl_sync(0xffffffffu, idx, 0);
    int d = __shfl_sync(0xffffffffu, idx, 1);

    float nrm = 0.f;
    if (lane == 0) nrm = __ldg(&g_norm[s]);
    nrm = __shfl_sync(0xffffffffu, nrm, 0);

    float4 v = reinterpret_cast<const float4*>(feat + (size_t)s * D)[lane];
    v.x *= nrm; v.y *= nrm; v.z *= nrm; v.w *= nrm;
    float* p = g_agg + (size_t)d * D + lane * 4;
    asm volatile("red.global.add.v4.f32 [%0], {%1,%2,%3,%4};"
                 :: "l"(p), "f"(v.x), "f"(v.y), "f"(v.z), "f"(v.w)
                 : "memory");
}

// ---------------------------------------------------------------------------
// Fused epilogue + GEMM:
//   h = agg*norm*(1-ALPHA) + ALPHA*feat_0   (computed during tile load)
//   out = h @ M + bias
// 128x128 block tile (K=128 in one shot), 256 threads, 8x8 register tiles.
// ---------------------------------------------------------------------------
__global__ __launch_bounds__(256) void gemm_kernel(
    const float* __restrict__ feat0,
    const float* __restrict__ bias,
    float* __restrict__ out, int n) {
    extern __shared__ float sh[];
    float* hT = sh;                // [D][LR]  hT[k][m]
    float* Ms = sh + D * LR;       // [D][LR]  Ms[k][c]

    int tid = threadIdx.x;

    for (int i = tid; i < D * D / 4; i += 256) {
        int k = i >> 5;
        int c4 = i & 31;
        float4 v = reinterpret_cast<const float4*>(g_M)[i];
        *reinterpret_cast<float4*>(&Ms[k * LR + c4 * 4]) = v;
    }

    int m = tid & 127;
    int half = tid >> 7;
    int row = blockIdx.x * BM + m;
    bool valid = row < n;
    float nrm = valid ? g_norm[row] : 0.f;
    float sc = nrm * (1.0f - ALPHA);
    const float4* ar = reinterpret_cast<const float4*>(g_agg + (size_t)row * D);
    const float4* fr = reinterpret_cast<const float4*>(feat0 + (size_t)row * D);
    float4 z = make_float4(0.f, 0.f, 0.f, 0.f);
    for (int j = half; j < 32; j += 2) {
        float4 a = valid ? ar[j] : z;
        float4 f = valid ? fr[j] : z;
        float4 h;
        h.x = a.x * sc + ALPHA * f.x;
        h.y = a.y * sc + ALPHA * f.y;
        h.z = a.z * sc + ALPHA * f.z;
        h.w = a.w * sc + ALPHA * f.w;
        int k = j * 4;
        hT[(k + 0) * LR + m] = h.x;
        hT[(k + 1) * LR + m] = h.y;
        hT[(k + 2) * LR + m] = h.z;
        hT[(k + 3) * LR + m] = h.w;
    }
    __syncthreads();

    int tx = tid & 15;
    int ty = tid >> 4;
    int tn0 = tx * 8;
    int tm0 = ty * 8;

    float acc[8][8];
#pragma unroll
    for (int i = 0; i < 8; i++)
#pragma unroll
        for (int j = 0; j < 8; j++) acc[i][j] = 0.f;

#pragma unroll 4
    for (int k = 0; k < D; k++) {
        float4 a0 = *reinterpret_cast<const float4*>(&hT[k * LR + tm0]);
        float4 a1 = *reinterpret_cast<const float4*>(&hT[k * LR + tm0 + 4]);
        float4 b0 = *reinterpret_cast<const float4*>(&Ms[k * LR + tn0]);
        float4 b1 = *reinterpret_cast<const float4*>(&Ms[k * LR + tn0 + 4]);
        float am[8] = {a0.x, a0.y, a0.z, a0.w, a1.x, a1.y, a1.z, a1.w};
        float bn[8] = {b0.x, b0.y, b0.z, b0.w, b1.x, b1.y, b1.z, b1.w};
#pragma unroll
        for (int i = 0; i < 8; i++)
#pragma unroll
            for (int j = 0; j < 8; j++)
                acc[i][j] += am[i] * bn[j];
    }

    float bv[8];
#pragma unroll
    for (int j = 0; j < 8; j++) bv[j] = __ldg(&bias[tn0 + j]);

#pragma unroll
    for (int i = 0; i < 8; i++) {
        int r = blockIdx.x * BM + tm0 + i;
        if (r < n) {
            float4 o0 = make_float4(acc[i][0] + bv[0], acc[i][1] + bv[1],
                                    acc[i][2] + bv[2], acc[i][3] + bv[3]);
            float4 o1 = make_float4(acc[i][4] + bv[4], acc[i][5] + bv[5],
                                    acc[i][6] + bv[6], acc[i][7] + bv[7]);
            float4* op = reinterpret_cast<float4*>(out + (size_t)r * D + tn0);
            op[0] = o0;
            op[1] = o1;
        }
    }
}

// ---------------------------------------------------------------------------
// kernel_launch: inputs per metadata order:
//   0 feat [N,128] f32, 1 feat_0 [N,128] f32, 2 weight1 [128,128] f32,
//   3 bias [128] f32, 4 src [E] i32, 5 dst [E] i32; out [N,128] f32
// ---------------------------------------------------------------------------
extern "C" void kernel_launch(void* const* d_in, const int* in_sizes, int n_in,
                              void* d_out, int out_size) {
    const float* feat  = (const float*)d_in[0];
    const float* feat0 = (const float*)d_in[1];
    const float* w1    = (const float*)d_in[2];
    const float* bias  = (const float*)d_in[3];
    const int*   src   = (const int*)d_in[4];
    const int*   dst   = (const int*)d_in[5];
    float* out = (float*)d_out;

    int n = in_sizes[0] / D;
    int E = in_sizes[4];
    const float BETA = 0.22314355f;  // log(1/4 + 1)

    zero_kernel<<<2048, 256>>>(n);
    degree_kernel<<<((E >> 2) + 255) / 256, 256>>>(dst, E);
    norm_and_m_kernel<<<(n + 255) / 256, 256>>>(w1, BETA, n);

    long long threads = (long long)E * 32;
    int sblocks = (int)((threads + 255) / 256);
    scatter_kernel<<<sblocks, 256>>>(feat, src, dst, E);

    int smem = 2 * D * LR * sizeof(float);  // ~135 KB
    cudaFuncSetAttribute(gemm_kernel, cudaFuncAttributeMaxDynamicSharedMemorySize, smem);
    gemm_kernel<<<(n + BM - 1) / BM, 256, smem>>>(feat0, bias, out, n);
}

// round 16
// speedup vs baseline: 1.0842x; 1.0842x over previous
#include <cuda_runtime.h>
#include <cuda_bf16.h>

#define D 128
#define N_MAX 50016
#define BM 128
#define LR (D + 4)   // padded shared row stride (floats)
#define EPW 8        // edges per warp in scatter

__device__ float g_deg[N_MAX];
__device__ float g_norm[N_MAX];
__device__ float g_agg[(size_t)N_MAX * D];
__device__ float g_M[D * D];

static constexpr float ALPHA = 0.1f;

// ---------------------------------------------------------------------------
// Zero scratch (agg + deg). Graph is replayed, so this runs every launch.
// ---------------------------------------------------------------------------
__global__ void zero_kernel(int n) {
    int i = blockIdx.x * blockDim.x + threadIdx.x;
    int stride = gridDim.x * blockDim.x;
    int tot4 = n * D / 4;
    float4 z = make_float4(0.f, 0.f, 0.f, 0.f);
    for (int j = i; j < tot4; j += stride)
        reinterpret_cast<float4*>(g_agg)[j] = z;
    for (int j = i; j < n; j += stride)
        g_deg[j] = 0.f;
}

// ---------------------------------------------------------------------------
// In-degree. 4 edges per thread via int4 load.
// ---------------------------------------------------------------------------
__global__ void degree_kernel(const int* __restrict__ dst, int E) {
    int t = blockIdx.x * blockDim.x + threadIdx.x;
    int e4 = E >> 2;
    if (t < e4) {
        int4 d = reinterpret_cast<const int4*>(dst)[t];
        atomicAdd(&g_deg[d.x], 1.0f);
        atomicAdd(&g_deg[d.y], 1.0f);
        atomicAdd(&g_deg[d.z], 1.0f);
        atomicAdd(&g_deg[d.w], 1.0f);
    }
    int tail = E & 3;
    if (t < tail) atomicAdd(&g_deg[dst[e4 * 4 + t]], 1.0f);
}

// ---------------------------------------------------------------------------
// norm = clip(deg,1)^-0.5, fused with M = (1-beta)*I + beta*W1
// ---------------------------------------------------------------------------
__global__ void norm_and_m_kernel(const float* __restrict__ w, float beta,
                                  int n) {
    int i = blockIdx.x * blockDim.x + threadIdx.x;
    if (i < n) g_norm[i] = rsqrtf(fmaxf(g_deg[i], 1.0f));
    if (i < D * D) {
        float v = beta * w[i];
        if ((i / D) == (i % D)) v += (1.0f - beta);
        g_M[i] = v;
    }
}

// ---------------------------------------------------------------------------
// Edge scatter: agg[dst] += feat[src] * norm[src]
// EPW=8 edges per warp. The R14 ncu showed the 1-edge/warp version was
// latency-bound (issue 32%, L2 50%): one serial chain idx->norm->row->RED
// per warp. Here lanes 0..7 batch-load the 8 src indices, lanes 8..15 the
// 8 dst, lanes 0..7 the 8 norms (one latency round amortized over 8 edges),
// then an unrolled loop issues 8 independent LDG.128 gathers before the
// 8 RED.128s -> ~8x per-warp MLP.
// ---------------------------------------------------------------------------
__global__ void scatter_kernel(const float* __restrict__ feat,
                               const int* __restrict__ src,
                               const int* __restrict__ dst, int E) {
    long long warp = (long long)blockIdx.x * (blockDim.x >> 5) + (threadIdx.x >> 5);
    int lane = threadIdx.x & 31;
    long long base = warp * EPW;
    if (base >= E) return;
    int cnt = (int)(((long long)E - base < EPW) ? (E - base) : EPW);

    // Batched index loads: lanes 0..7 -> src, lanes 8..15 -> dst
    int sidx = 0;
    if (lane < cnt) sidx = __ldg(&src[base + lane]);
    else if (lane >= 8 && lane < 8 + cnt) sidx = __ldg(&dst[base + lane - 8]);

    // Batched norm loads (lanes 0..7, using their own src index)
    float nrm = 0.f;
    if (lane < cnt) nrm = __ldg(&g_norm[sidx]);

    // Phase 1: issue all row gathers (independent -> 8 LDG.128 in flight)
    float4 v[EPW];
    int dIdx[EPW];
#pragma unroll
    for (int i = 0; i < EPW; i++) {
        int s = __shfl_sync(0xffffffffu, sidx, i);
        dIdx[i] = __shfl_sync(0xffffffffu, sidx, 8 + i);
        float nm = __shfl_sync(0xffffffffu, nrm, i);
        if (i < cnt) {
            float4 t = reinterpret_cast<const float4*>(feat + (size_t)s * D)[lane];
            v[i].x = t.x * nm; v[i].y = t.y * nm;
            v[i].z = t.z * nm; v[i].w = t.w * nm;
        }
    }

    // Phase 2: fire the REDs (no return -> non-blocking)
#pragma unroll
    for (int i = 0; i < EPW; i++) {
        if (i < cnt) {
            float* p = g_agg + (size_t)dIdx[i] * D + lane * 4;
            asm volatile("red.global.add.v4.f32 [%0], {%1,%2,%3,%4};"
                         :: "l"(p), "f"(v[i].x), "f"(v[i].y), "f"(v[i].z), "f"(v[i].w)
                         : "memory");
        }
    }
}

// ---------------------------------------------------------------------------
// Fused epilogue + GEMM:
//   h = agg*norm*(1-ALPHA) + ALPHA*feat_0   (computed during tile load)
//   out = h @ M + bias
// 128x128 block tile (K=128 in one shot), 256 threads, 8x8 register tiles.
// ---------------------------------------------------------------------------
__global__ __launch_bounds__(256) void gemm_kernel(
    const float* __restrict__ feat0,
    const float* __restrict__ bias,
    float* __restrict__ out, int n) {
    extern __shared__ float sh[];
    float* hT = sh;                // [D][LR]  hT[k][m]
    float* Ms = sh + D * LR;       // [D][LR]  Ms[k][c]

    int tid = threadIdx.x;

    for (int i = tid; i < D * D / 4; i += 256) {
        int k = i >> 5;
        int c4 = i & 31;
        float4 v = reinterpret_cast<const float4*>(g_M)[i];
        *reinterpret_cast<float4*>(&Ms[k * LR + c4 * 4]) = v;
    }

    int m = tid & 127;
    int half = tid >> 7;
    int row = blockIdx.x * BM + m;
    bool valid = row < n;
    float nrm = valid ? g_norm[row] : 0.f;
    float sc = nrm * (1.0f - ALPHA);
    const float4* ar = reinterpret_cast<const float4*>(g_agg + (size_t)row * D);
    const float4* fr = reinterpret_cast<const float4*>(feat0 + (size_t)row * D);
    float4 z = make_float4(0.f, 0.f, 0.f, 0.f);
    for (int j = half; j < 32; j += 2) {
        float4 a = valid ? ar[j] : z;
        float4 f = valid ? fr[j] : z;
        float4 h;
        h.x = a.x * sc + ALPHA * f.x;
        h.y = a.y * sc + ALPHA * f.y;
        h.z = a.z * sc + ALPHA * f.z;
        h.w = a.w * sc + ALPHA * f.w;
        int k = j * 4;
        hT[(k + 0) * LR + m] = h.x;
        hT[(k + 1) * LR + m] = h.y;
        hT[(k + 2) * LR + m] = h.z;
        hT[(k + 3) * LR + m] = h.w;
    }
    __syncthreads();

    int tx = tid & 15;
    int ty = tid >> 4;
    int tn0 = tx * 8;
    int tm0 = ty * 8;

    float acc[8][8];
#pragma unroll
    for (int i = 0; i < 8; i++)
#pragma unroll
        for (int j = 0; j < 8; j++) acc[i][j] = 0.f;

#pragma unroll 4
    for (int k = 0; k < D; k++) {
        float4 a0 = *reinterpret_cast<const float4*>(&hT[k * LR + tm0]);
        float4 a1 = *reinterpret_cast<const float4*>(&hT[k * LR + tm0 + 4]);
        float4 b0 = *reinterpret_cast<const float4*>(&Ms[k * LR + tn0]);
        float4 b1 = *reinterpret_cast<const float4*>(&Ms[k * LR + tn0 + 4]);
        float am[8] = {a0.x, a0.y, a0.z, a0.w, a1.x, a1.y, a1.z, a1.w};
        float bn[8] = {b0.x, b0.y, b0.z, b0.w, b1.x, b1.y, b1.z, b1.w};
#pragma unroll
        for (int i = 0; i < 8; i++)
#pragma unroll
            for (int j = 0; j < 8; j++)
                acc[i][j] += am[i] * bn[j];
    }

    float bv[8];
#pragma unroll
    for (int j = 0; j < 8; j++) bv[j] = __ldg(&bias[tn0 + j]);

#pragma unroll
    for (int i = 0; i < 8; i++) {
        int r = blockIdx.x * BM + tm0 + i;
        if (r < n) {
            float4 o0 = make_float4(acc[i][0] + bv[0], acc[i][1] + bv[1],
                                    acc[i][2] + bv[2], acc[i][3] + bv[3]);
            float4 o1 = make_float4(acc[i][4] + bv[4], acc[i][5] + bv[5],
                                    acc[i][6] + bv[6], acc[i][7] + bv[7]);
            float4* op = reinterpret_cast<float4*>(out + (size_t)r * D + tn0);
            op[0] = o0;
            op[1] = o1;
        }
    }
}

// ---------------------------------------------------------------------------
// kernel_launch: inputs per metadata order:
//   0 feat [N,128] f32, 1 feat_0 [N,128] f32, 2 weight1 [128,128] f32,
//   3 bias [128] f32, 4 src [E] i32, 5 dst [E] i32; out [N,128] f32
// ---------------------------------------------------------------------------
extern "C" void kernel_launch(void* const* d_in, const int* in_sizes, int n_in,
                              void* d_out, int out_size) {
    const float* feat  = (const float*)d_in[0];
    const float* feat0 = (const float*)d_in[1];
    const float* w1    = (const float*)d_in[2];
    const float* bias  = (const float*)d_in[3];
    const int*   src   = (const int*)d_in[4];
    const int*   dst   = (const int*)d_in[5];
    float* out = (float*)d_out;

    int n = in_sizes[0] / D;
    int E = in_sizes[4];
    const float BETA = 0.22314355f;  // log(1/4 + 1)

    zero_kernel<<<2048, 256>>>(n);
    degree_kernel<<<((E >> 2) + 255) / 256, 256>>>(dst, E);
    norm_and_m_kernel<<<(n + 255) / 256, 256>>>(w1, BETA, n);

    // EPW edges per warp, 8 warps per block
    long long warps = ((long long)E + EPW - 1) / EPW;
    int sblocks = (int)((warps + 7) / 8);
    scatter_kernel<<<sblocks, 256>>>(feat, src, dst, E);

    int smem = 2 * D * LR * sizeof(float);  // ~135 KB
    cudaFuncSetAttribute(gemm_kernel, cudaFuncAttributeMaxDynamicSharedMemorySize, smem);
    gemm_kernel<<<(n + BM - 1) / BM, 256, smem>>>(feat0, bias, out, n);
}